// round 1
// baseline (speedup 1.0000x reference)
#include <cuda_runtime.h>
#include <math.h>

#define B_   8
#define T_   1024
#define C_   2048
#define H_   16
#define HKV_ 4
#define HD_  128
#define CKV_ 512

// Scratch (device globals: allocation-free per harness rules)
__device__ float g_q[(size_t)B_ * T_ * C_];    // 64 MB
__device__ float g_k[(size_t)B_ * T_ * CKV_];  // 16 MB
__device__ float g_v[(size_t)B_ * T_ * CKV_];  // 16 MB
__device__ float g_y[(size_t)B_ * T_ * C_];    // 64 MB

// ---------------------------------------------------------------------------
// SIMT fp32 GEMM: C[M,N] = A[M,K] @ B[K,N], all row-major.
// 128x128 block tile, BK=16, 256 threads, 8x8 per-thread register tile.
// M % 128 == 0, N % 128 == 0, K % 16 == 0 (true for all our shapes).
// ---------------------------------------------------------------------------
__global__ __launch_bounds__(256) void sgemm128(
    const float* __restrict__ A, const float* __restrict__ Bm,
    float* __restrict__ C, int M, int N, int K)
{
    __shared__ float As[16][128];  // [k][m] (A stored transposed)
    __shared__ float Bs[16][128];  // [k][n]

    const int tid  = threadIdx.x;
    const int tRow = tid >> 4;     // 0..15
    const int tCol = tid & 15;     // 0..15
    const int m0 = blockIdx.y * 128;
    const int n0 = blockIdx.x * 128;

    float acc[8][8];
#pragma unroll
    for (int i = 0; i < 8; i++)
#pragma unroll
        for (int j = 0; j < 8; j++) acc[i][j] = 0.f;

    const float* Ab = A + (size_t)m0 * K;
    const float* Bb = Bm + n0;

    for (int k0 = 0; k0 < K; k0 += 16) {
        // Load A tile: 128 rows x 16 k -> As[k][row]; 512 float4, 2/thread
#pragma unroll
        for (int it = 0; it < 2; it++) {
            int v   = tid * 2 + it;
            int row = v >> 2;
            int kc  = (v & 3) << 2;
            float4 a = *reinterpret_cast<const float4*>(Ab + (size_t)row * K + k0 + kc);
            As[kc + 0][row] = a.x;
            As[kc + 1][row] = a.y;
            As[kc + 2][row] = a.z;
            As[kc + 3][row] = a.w;
        }
        // Load B tile: 16 k x 128 n; 512 float4, 2/thread, coalesced
#pragma unroll
        for (int it = 0; it < 2; it++) {
            int v  = tid * 2 + it;
            int kr = v >> 5;
            int nc = (v & 31) << 2;
            *reinterpret_cast<float4*>(&Bs[kr][nc]) =
                *reinterpret_cast<const float4*>(Bb + (size_t)(k0 + kr) * N + nc);
        }
        __syncthreads();

#pragma unroll
        for (int kk = 0; kk < 16; kk++) {
            float ra[8], rb[8];
            *(float4*)(ra)     = *(const float4*)&As[kk][tRow * 8];
            *(float4*)(ra + 4) = *(const float4*)&As[kk][tRow * 8 + 4];
            *(float4*)(rb)     = *(const float4*)&Bs[kk][tCol * 8];
            *(float4*)(rb + 4) = *(const float4*)&Bs[kk][tCol * 8 + 4];
#pragma unroll
            for (int i = 0; i < 8; i++)
#pragma unroll
                for (int j = 0; j < 8; j++)
                    acc[i][j] = fmaf(ra[i], rb[j], acc[i][j]);
        }
        __syncthreads();
    }

#pragma unroll
    for (int i = 0; i < 8; i++) {
        float* Cr = C + (size_t)(m0 + tRow * 8 + i) * N + n0 + tCol * 8;
        *(float4*)Cr       = make_float4(acc[i][0], acc[i][1], acc[i][2], acc[i][3]);
        *(float4*)(Cr + 4) = make_float4(acc[i][4], acc[i][5], acc[i][6], acc[i][7]);
    }
}

// ---------------------------------------------------------------------------
// RoPE: rotates pairs (d, d+64) of each 128-wide head, in place.
// width = nheads * 128. sin/cos: [1024, 128].
// ---------------------------------------------------------------------------
__global__ void rope_kernel(float* __restrict__ p, const float* __restrict__ sp,
                            const float* __restrict__ cp, int nheads, int width,
                            int total)
{
    int idx = blockIdx.x * blockDim.x + threadIdx.x;
    if (idx >= total) return;
    int i = idx & 63;
    int h = (idx >> 6) % nheads;
    int t = (idx / (64 * nheads)) % T_;
    int b = idx / (64 * nheads * T_);
    size_t base = ((size_t)(b * T_ + t)) * width + h * HD_ + i;
    float a = p[base];
    float c = p[base + 64];
    float s0 = sp[t * HD_ + i],      c0 = cp[t * HD_ + i];
    float s1 = sp[t * HD_ + 64 + i], c1 = cp[t * HD_ + 64 + i];
    p[base]      = a * c0 - c * s0;
    p[base + 64] = c * c1 + a * s1;
}

// ---------------------------------------------------------------------------
// Flash attention (causal, online softmax). One CTA = 64 q rows of one (b,h).
// Q,K stored transposed in smem ([d][row], stride 68 for fp32 float4 align).
// S tile 64x64 in registers (4x4/thread, 16x16 thread grid), P staged via smem.
// O tile 64x128 in registers (4 rows x 8 cols / thread).
// ---------------------------------------------------------------------------
#define QS_  68
#define PS_  65
#define ATTN_SMEM_BYTES ((128 * QS_ * 2 + 64 * 128 + 64 * PS_) * 4)

__global__ __launch_bounds__(256) void attn_kernel()
{
    extern __shared__ float sm[];
    float* Qs = sm;                  // [128][QS_]  (d-major)
    float* Ks = Qs + 128 * QS_;      // [128][QS_]  (d-major)
    float* Vs = Ks + 128 * QS_;      // [64][128]   (row-major)
    float* Ps = Vs + 64 * 128;       // [64][PS_]

    const int qt  = blockIdx.x;      // 0..15
    const int h   = blockIdx.y;
    const int b   = blockIdx.z;
    const int q0  = qt * 64;
    const int kvh = h & 3;           // GQA: kv head = h % 4
    const int tid = threadIdx.x;
    const int tRow = tid >> 4;
    const int tCol = tid & 15;

    const float scale = 0.08838834764831845f;  // 1/sqrt(128)

    // Load+scale Q tile (transposed into smem)
    const float* qg = g_q + ((size_t)(b * T_ + q0)) * C_ + h * HD_;
    for (int v = tid; v < 64 * 32; v += 256) {
        int r  = v >> 5;
        int d4 = (v & 31) << 2;
        float4 a = *(const float4*)(qg + (size_t)r * C_ + d4);
        Qs[(d4 + 0) * QS_ + r] = a.x * scale;
        Qs[(d4 + 1) * QS_ + r] = a.y * scale;
        Qs[(d4 + 2) * QS_ + r] = a.z * scale;
        Qs[(d4 + 3) * QS_ + r] = a.w * scale;
    }

    float o[4][8];
    float mrow[4], lrow[4];
#pragma unroll
    for (int i = 0; i < 4; i++) {
        mrow[i] = -1e30f;
        lrow[i] = 0.f;
#pragma unroll
        for (int c = 0; c < 8; c++) o[i][c] = 0.f;
    }

    const float* kg = g_k + (size_t)b * T_ * CKV_ + kvh * HD_;
    const float* vg = g_v + (size_t)b * T_ * CKV_ + kvh * HD_;

    for (int kt = 0; kt <= qt; kt++) {
        const int k0 = kt * 64;
        __syncthreads();  // protect Ks/Vs/Ps from previous iteration readers
        for (int v = tid; v < 64 * 32; v += 256) {
            int r  = v >> 5;
            int d4 = (v & 31) << 2;
            float4 a = *(const float4*)(kg + (size_t)(k0 + r) * CKV_ + d4);
            Ks[(d4 + 0) * QS_ + r] = a.x;
            Ks[(d4 + 1) * QS_ + r] = a.y;
            Ks[(d4 + 2) * QS_ + r] = a.z;
            Ks[(d4 + 3) * QS_ + r] = a.w;
            *(float4*)(Vs + r * 128 + d4) =
                *(const float4*)(vg + (size_t)(k0 + r) * CKV_ + d4);
        }
        __syncthreads();

        // S = (Q*scale) @ K^T, 4x4 per thread
        float s[4][4];
#pragma unroll
        for (int i = 0; i < 4; i++)
#pragma unroll
            for (int j = 0; j < 4; j++) s[i][j] = 0.f;

        for (int d = 0; d < 128; d++) {
            float qa[4], kb[4];
            *(float4*)qa = *(const float4*)(Qs + d * QS_ + tRow * 4);
            *(float4*)kb = *(const float4*)(Ks + d * QS_ + tCol * 4);
#pragma unroll
            for (int i = 0; i < 4; i++)
#pragma unroll
                for (int j = 0; j < 4; j++)
                    s[i][j] = fmaf(qa[i], kb[j], s[i][j]);
        }

        if (kt == qt) {  // causal mask on diagonal tile only
#pragma unroll
            for (int i = 0; i < 4; i++)
#pragma unroll
                for (int j = 0; j < 4; j++)
                    if (k0 + tCol * 4 + j > q0 + tRow * 4 + i) s[i][j] = -1e30f;
        }

        // Online softmax per row (rows shared by 16 lanes of same tRow half-warp)
#pragma unroll
        for (int i = 0; i < 4; i++) {
            float rm = fmaxf(fmaxf(s[i][0], s[i][1]), fmaxf(s[i][2], s[i][3]));
#pragma unroll
            for (int off = 8; off; off >>= 1)
                rm = fmaxf(rm, __shfl_xor_sync(0xffffffffu, rm, off, 16));
            float mn = fmaxf(mrow[i], rm);
            float al = __expf(mrow[i] - mn);
            mrow[i] = mn;
            float rs = 0.f;
#pragma unroll
            for (int j = 0; j < 4; j++) {
                float pv = __expf(s[i][j] - mn);
                rs += pv;
                Ps[(tRow * 4 + i) * PS_ + tCol * 4 + j] = pv;
            }
#pragma unroll
            for (int off = 8; off; off >>= 1)
                rs += __shfl_xor_sync(0xffffffffu, rs, off, 16);
            lrow[i] = lrow[i] * al + rs;
#pragma unroll
            for (int c = 0; c < 8; c++) o[i][c] *= al;
        }
        __syncthreads();

        // O += P @ V  (each thread: rows tRow*4.., cols tCol*8..)
#pragma unroll 2
        for (int kk = 0; kk < 64; kk++) {
            float vv[8];
            *(float4*)vv       = *(const float4*)(Vs + kk * 128 + tCol * 8);
            *(float4*)(vv + 4) = *(const float4*)(Vs + kk * 128 + tCol * 8 + 4);
#pragma unroll
            for (int i = 0; i < 4; i++) {
                float pp = Ps[(tRow * 4 + i) * PS_ + kk];
#pragma unroll
                for (int c = 0; c < 8; c++)
                    o[i][c] = fmaf(pp, vv[c], o[i][c]);
            }
        }
    }

    // Normalize + write y
    float* yg = g_y + ((size_t)(b * T_ + q0)) * C_ + h * HD_;
#pragma unroll
    for (int i = 0; i < 4; i++) {
        float inv = 1.f / lrow[i];
        float* dst = yg + (size_t)(tRow * 4 + i) * C_ + tCol * 8;
        *(float4*)dst       = make_float4(o[i][0] * inv, o[i][1] * inv,
                                          o[i][2] * inv, o[i][3] * inv);
        *(float4*)(dst + 4) = make_float4(o[i][4] * inv, o[i][5] * inv,
                                          o[i][6] * inv, o[i][7] * inv);
    }
}

// ---------------------------------------------------------------------------
extern "C" void kernel_launch(void* const* d_in, const int* in_sizes, int n_in,
                              void* d_out, int out_size)
{
    const float* x  = (const float*)d_in[0];
    const float* wq = (const float*)d_in[1];
    const float* wk = (const float*)d_in[2];
    const float* wv = (const float*)d_in[3];
    const float* wo = (const float*)d_in[4];
    const float* sp = (const float*)d_in[5];
    const float* cp = (const float*)d_in[6];
    float* out = (float*)d_out;

    float *qp, *kp, *vp, *yp;
    cudaGetSymbolAddress((void**)&qp, g_q);
    cudaGetSymbolAddress((void**)&kp, g_k);
    cudaGetSymbolAddress((void**)&vp, g_v);
    cudaGetSymbolAddress((void**)&yp, g_y);

    cudaFuncSetAttribute(attn_kernel, cudaFuncAttributeMaxDynamicSharedMemorySize,
                         ATTN_SMEM_BYTES);

    const int M = B_ * T_;  // 8192
    dim3 blk(256);

    // QKV projections
    sgemm128<<<dim3(C_ / 128, M / 128), blk>>>(x, wq, qp, M, C_, C_);
    sgemm128<<<dim3(CKV_ / 128, M / 128), blk>>>(x, wk, kp, M, CKV_, C_);
    sgemm128<<<dim3(CKV_ / 128, M / 128), blk>>>(x, wv, vp, M, CKV_, C_);

    // RoPE on q and k
    int tq = B_ * T_ * H_ * 64;
    rope_kernel<<<(tq + 255) / 256, 256>>>(qp, sp, cp, H_, C_, tq);
    int tk = B_ * T_ * HKV_ * 64;
    rope_kernel<<<(tk + 255) / 256, 256>>>(kp, sp, cp, HKV_, CKV_, tk);

    // Causal flash attention
    attn_kernel<<<dim3(T_ / 64, H_, B_), 256, ATTN_SMEM_BYTES>>>();

    // Output projection
    sgemm128<<<dim3(C_ / 128, M / 128), blk>>>(yp, wo, out, M, C_, C_);
}

// round 6
// speedup vs baseline: 1.1898x; 1.1898x over previous
#include <cuda_runtime.h>
#include <cuda_bf16.h>
#include <mma.h>
#include <cstdint>
#include <math.h>

using namespace nvcuda;

#define B_   8
#define T_   1024
#define C_   2048
#define H_   16
#define HKV_ 4
#define HD_  128
#define CKV_ 512

// Scratch (device globals: allocation-free per harness rules)
__device__ float g_q[(size_t)B_ * T_ * C_];    // 64 MB
__device__ float g_k[(size_t)B_ * T_ * CKV_];  // 16 MB
__device__ float g_v[(size_t)B_ * T_ * CKV_];  // 16 MB
__device__ float g_y[(size_t)B_ * T_ * C_];    // 64 MB

// ---------------------------------------------------------------------------
// Tensor-core GEMM via wmma (legacy HMMA path; tcgen05 PTX is rejected by the
// harness's sm_103 (non-'a') ptxas target).
// C[M,N] = A[M,K] @ B[K,N], fp32 in/out.
// Precision: bf16 split, A=Ahi+Alo, B=Bhi+Blo; acc += AhiBhi + AhiBlo + AloBhi
// (fp32 accumulate). Dropped AloBlo ~2^-16 relative -> rel_err ~1e-5.
// Tiles: BM=128, BN=128, BK=32; 256 threads = 8 warps (4x2), warp = 32x64.
// ---------------------------------------------------------------------------
#define BM 128
#define BN 128
#define BK 32
#define LDA 40    // BK + 8 pad (bf16 elems)
#define LDB 136   // BN + 8 pad

__global__ __launch_bounds__(256) void hgemm(const float* __restrict__ A,
                                             const float* __restrict__ Bm,
                                             float* __restrict__ C,
                                             int M, int N, int K)
{
    __shared__ __nv_bfloat16 sAhi[BM * LDA];
    __shared__ __nv_bfloat16 sAlo[BM * LDA];
    __shared__ __nv_bfloat16 sBhi[BK * LDB];
    __shared__ __nv_bfloat16 sBlo[BK * LDB];

    const int tid = threadIdx.x;
    const int w   = tid >> 5;
    const int warpM = w & 3;        // 0..3  (32 rows each)
    const int warpN = w >> 2;       // 0..1  (64 cols each)
    const int m0 = blockIdx.y * BM;
    const int n0 = blockIdx.x * BN;

    wmma::fragment<wmma::accumulator, 16, 16, 16, float> acc[2][4];
#pragma unroll
    for (int mt = 0; mt < 2; mt++)
#pragma unroll
        for (int nt = 0; nt < 4; nt++)
            wmma::fill_fragment(acc[mt][nt], 0.0f);

    // Per-thread load coordinates (4 float4 each for A and B per chunk)
    //   A: v = it*256 + tid; row = v>>3 (0..127), k4 = v&7 (float4 within BK)
    //   B: v = it*256 + tid; row = v>>5 (0..31),  n4 = v&31
    float4 ra[4], rb[4];

    const int NCH = K / BK;

#define LDG_CHUNK(K0) do {                                                    \
        _Pragma("unroll")                                                     \
        for (int it = 0; it < 4; it++) {                                      \
            int v = it * 256 + tid;                                           \
            int arow = v >> 3, ak4 = v & 7;                                   \
            ra[it] = *(const float4*)(A + (size_t)(m0 + arow) * K + (K0) + ak4 * 4); \
            int brow = v >> 5, bn4 = v & 31;                                  \
            rb[it] = *(const float4*)(Bm + (size_t)((K0) + brow) * N + n0 + bn4 * 4); \
        }                                                                     \
    } while (0)

#define STS_CHUNK() do {                                                      \
        _Pragma("unroll")                                                     \
        for (int it = 0; it < 4; it++) {                                      \
            int v = it * 256 + tid;                                           \
            int arow = v >> 3, ak4 = v & 7;                                   \
            const float av[4] = {ra[it].x, ra[it].y, ra[it].z, ra[it].w};     \
            _Pragma("unroll")                                                 \
            for (int j = 0; j < 4; j++) {                                     \
                float x = av[j];                                              \
                __nv_bfloat16 h = __float2bfloat16_rn(x);                     \
                int idx = arow * LDA + ak4 * 4 + j;                           \
                sAhi[idx] = h;                                                \
                sAlo[idx] = __float2bfloat16_rn(x - __bfloat162float(h));     \
            }                                                                 \
            int brow = v >> 5, bn4 = v & 31;                                  \
            const float bv[4] = {rb[it].x, rb[it].y, rb[it].z, rb[it].w};     \
            _Pragma("unroll")                                                 \
            for (int j = 0; j < 4; j++) {                                     \
                float x = bv[j];                                              \
                __nv_bfloat16 h = __float2bfloat16_rn(x);                     \
                int idx = brow * LDB + bn4 * 4 + j;                           \
                sBhi[idx] = h;                                                \
                sBlo[idx] = __float2bfloat16_rn(x - __bfloat162float(h));     \
            }                                                                 \
        }                                                                     \
    } while (0)

    LDG_CHUNK(0);

    for (int c = 0; c < NCH; c++) {
        STS_CHUNK();
        __syncthreads();
        if (c + 1 < NCH) LDG_CHUNK((c + 1) * BK);   // prefetch, hidden by MMAs

#pragma unroll
        for (int ks = 0; ks < 2; ks++) {
            wmma::fragment<wmma::matrix_a, 16, 16, 16, __nv_bfloat16, wmma::row_major> ahi[2], alo[2];
            wmma::fragment<wmma::matrix_b, 16, 16, 16, __nv_bfloat16, wmma::row_major> bhi[4], blo[4];
#pragma unroll
            for (int mt = 0; mt < 2; mt++) {
                const __nv_bfloat16* ap = &sAhi[(warpM * 32 + mt * 16) * LDA + ks * 16];
                wmma::load_matrix_sync(ahi[mt], ap, LDA);
                wmma::load_matrix_sync(alo[mt], ap + (sAlo - sAhi), LDA);
            }
#pragma unroll
            for (int nt = 0; nt < 4; nt++) {
                const __nv_bfloat16* bp = &sBhi[(ks * 16) * LDB + warpN * 64 + nt * 16];
                wmma::load_matrix_sync(bhi[nt], bp, LDB);
                wmma::load_matrix_sync(blo[nt], bp + (sBlo - sBhi), LDB);
            }
#pragma unroll
            for (int mt = 0; mt < 2; mt++)
#pragma unroll
                for (int nt = 0; nt < 4; nt++) {
                    wmma::mma_sync(acc[mt][nt], ahi[mt], bhi[nt], acc[mt][nt]);
                    wmma::mma_sync(acc[mt][nt], ahi[mt], blo[nt], acc[mt][nt]);
                    wmma::mma_sync(acc[mt][nt], alo[mt], bhi[nt], acc[mt][nt]);
                }
        }
        __syncthreads();
    }

#pragma unroll
    for (int mt = 0; mt < 2; mt++)
#pragma unroll
        for (int nt = 0; nt < 4; nt++) {
            float* cp = C + (size_t)(m0 + warpM * 32 + mt * 16) * N
                          + n0 + warpN * 64 + nt * 16;
            wmma::store_matrix_sync(cp, acc[mt][nt], N, wmma::mem_row_major);
        }
#undef LDG_CHUNK
#undef STS_CHUNK
}

// ---------------------------------------------------------------------------
// RoPE: rotates pairs (d, d+64) of each 128-wide head, in place.
// ---------------------------------------------------------------------------
__global__ void rope_kernel(float* __restrict__ p, const float* __restrict__ sp,
                            const float* __restrict__ cp, int nheads, int width,
                            int total)
{
    int idx = blockIdx.x * blockDim.x + threadIdx.x;
    if (idx >= total) return;
    int i = idx & 63;
    int h = (idx >> 6) % nheads;
    int t = (idx / (64 * nheads)) % T_;
    int b = idx / (64 * nheads * T_);
    size_t base = ((size_t)(b * T_ + t)) * width + h * HD_ + i;
    float a = p[base];
    float c = p[base + 64];
    float s0 = sp[t * HD_ + i],      c0 = cp[t * HD_ + i];
    float s1 = sp[t * HD_ + 64 + i], c1 = cp[t * HD_ + 64 + i];
    p[base]      = a * c0 - c * s0;
    p[base + 64] = c * c1 + a * s1;
}

// ---------------------------------------------------------------------------
// Flash attention (causal, online softmax). One CTA = 64 q rows of one (b,h).
// ---------------------------------------------------------------------------
#define QS_  68
#define PS_  65
#define ATTN_SMEM_BYTES ((128 * QS_ * 2 + 64 * 128 + 64 * PS_) * 4)

__global__ __launch_bounds__(256) void attn_kernel()
{
    extern __shared__ float sm[];
    float* Qs = sm;                  // [128][QS_]  (d-major)
    float* Ks = Qs + 128 * QS_;      // [128][QS_]  (d-major)
    float* Vs = Ks + 128 * QS_;      // [64][128]   (row-major)
    float* Ps = Vs + 64 * 128;       // [64][PS_]

    const int qt  = blockIdx.x;
    const int h   = blockIdx.y;
    const int b   = blockIdx.z;
    const int q0  = qt * 64;
    const int kvh = h & 3;           // GQA: kv head = h % 4
    const int tid = threadIdx.x;
    const int tRow = tid >> 4;
    const int tCol = tid & 15;

    const float scale = 0.08838834764831845f;  // 1/sqrt(128)

    const float* qg = g_q + ((size_t)(b * T_ + q0)) * C_ + h * HD_;
    for (int v = tid; v < 64 * 32; v += 256) {
        int r  = v >> 5;
        int d4 = (v & 31) << 2;
        float4 a = *(const float4*)(qg + (size_t)r * C_ + d4);
        Qs[(d4 + 0) * QS_ + r] = a.x * scale;
        Qs[(d4 + 1) * QS_ + r] = a.y * scale;
        Qs[(d4 + 2) * QS_ + r] = a.z * scale;
        Qs[(d4 + 3) * QS_ + r] = a.w * scale;
    }

    float o[4][8];
    float mrow[4], lrow[4];
#pragma unroll
    for (int i = 0; i < 4; i++) {
        mrow[i] = -1e30f;
        lrow[i] = 0.f;
#pragma unroll
        for (int c = 0; c < 8; c++) o[i][c] = 0.f;
    }

    const float* kg = g_k + (size_t)b * T_ * CKV_ + kvh * HD_;
    const float* vg = g_v + (size_t)b * T_ * CKV_ + kvh * HD_;

    for (int kt = 0; kt <= qt; kt++) {
        const int k0 = kt * 64;
        __syncthreads();
        for (int v = tid; v < 64 * 32; v += 256) {
            int r  = v >> 5;
            int d4 = (v & 31) << 2;
            float4 a = *(const float4*)(kg + (size_t)(k0 + r) * CKV_ + d4);
            Ks[(d4 + 0) * QS_ + r] = a.x;
            Ks[(d4 + 1) * QS_ + r] = a.y;
            Ks[(d4 + 2) * QS_ + r] = a.z;
            Ks[(d4 + 3) * QS_ + r] = a.w;
            *(float4*)(Vs + r * 128 + d4) =
                *(const float4*)(vg + (size_t)(k0 + r) * CKV_ + d4);
        }
        __syncthreads();

        float s[4][4];
#pragma unroll
        for (int i = 0; i < 4; i++)
#pragma unroll
            for (int j = 0; j < 4; j++) s[i][j] = 0.f;

        for (int d = 0; d < 128; d++) {
            float qa[4], kb[4];
            *(float4*)qa = *(const float4*)(Qs + d * QS_ + tRow * 4);
            *(float4*)kb = *(const float4*)(Ks + d * QS_ + tCol * 4);
#pragma unroll
            for (int i = 0; i < 4; i++)
#pragma unroll
                for (int j = 0; j < 4; j++)
                    s[i][j] = fmaf(qa[i], kb[j], s[i][j]);
        }

        if (kt == qt) {
#pragma unroll
            for (int i = 0; i < 4; i++)
#pragma unroll
                for (int j = 0; j < 4; j++)
                    if (k0 + tCol * 4 + j > q0 + tRow * 4 + i) s[i][j] = -1e30f;
        }

#pragma unroll
        for (int i = 0; i < 4; i++) {
            float rm = fmaxf(fmaxf(s[i][0], s[i][1]), fmaxf(s[i][2], s[i][3]));
#pragma unroll
            for (int off = 8; off; off >>= 1)
                rm = fmaxf(rm, __shfl_xor_sync(0xffffffffu, rm, off, 16));
            float mn = fmaxf(mrow[i], rm);
            float al = __expf(mrow[i] - mn);
            mrow[i] = mn;
            float rs = 0.f;
#pragma unroll
            for (int j = 0; j < 4; j++) {
                float pv = __expf(s[i][j] - mn);
                rs += pv;
                Ps[(tRow * 4 + i) * PS_ + tCol * 4 + j] = pv;
            }
#pragma unroll
            for (int off = 8; off; off >>= 1)
                rs += __shfl_xor_sync(0xffffffffu, rs, off, 16);
            lrow[i] = lrow[i] * al + rs;
#pragma unroll
            for (int c = 0; c < 8; c++) o[i][c] *= al;
        }
        __syncthreads();

#pragma unroll 2
        for (int kk = 0; kk < 64; kk++) {
            float vv[8];
            *(float4*)vv       = *(const float4*)(Vs + kk * 128 + tCol * 8);
            *(float4*)(vv + 4) = *(const float4*)(Vs + kk * 128 + tCol * 8 + 4);
#pragma unroll
            for (int i = 0; i < 4; i++) {
                float pp = Ps[(tRow * 4 + i) * PS_ + kk];
#pragma unroll
                for (int c = 0; c < 8; c++)
                    o[i][c] = fmaf(pp, vv[c], o[i][c]);
            }
        }
    }

    float* yg = g_y + ((size_t)(b * T_ + q0)) * C_ + h * HD_;
#pragma unroll
    for (int i = 0; i < 4; i++) {
        float inv = 1.f / lrow[i];
        float* dst = yg + (size_t)(tRow * 4 + i) * C_ + tCol * 8;
        *(float4*)dst       = make_float4(o[i][0] * inv, o[i][1] * inv,
                                          o[i][2] * inv, o[i][3] * inv);
        *(float4*)(dst + 4) = make_float4(o[i][4] * inv, o[i][5] * inv,
                                          o[i][6] * inv, o[i][7] * inv);
    }
}

// ---------------------------------------------------------------------------
extern "C" void kernel_launch(void* const* d_in, const int* in_sizes, int n_in,
                              void* d_out, int out_size)
{
    const float* x  = (const float*)d_in[0];
    const float* wq = (const float*)d_in[1];
    const float* wk = (const float*)d_in[2];
    const float* wv = (const float*)d_in[3];
    const float* wo = (const float*)d_in[4];
    const float* sp = (const float*)d_in[5];
    const float* cp = (const float*)d_in[6];
    float* out = (float*)d_out;

    float *qp, *kp, *vp, *yp;
    cudaGetSymbolAddress((void**)&qp, g_q);
    cudaGetSymbolAddress((void**)&kp, g_k);
    cudaGetSymbolAddress((void**)&vp, g_v);
    cudaGetSymbolAddress((void**)&yp, g_y);

    cudaFuncSetAttribute(attn_kernel, cudaFuncAttributeMaxDynamicSharedMemorySize,
                         ATTN_SMEM_BYTES);

    const int M = B_ * T_;  // 8192

    // QKV projections (tensor-core bf16-split GEMMs; B consumed as [K,N] directly)
    hgemm<<<dim3(C_ / BN,  M / BM), 256>>>(x, wq, qp, M, C_, C_);
    hgemm<<<dim3(CKV_ / BN, M / BM), 256>>>(x, wk, kp, M, CKV_, C_);
    hgemm<<<dim3(CKV_ / BN, M / BM), 256>>>(x, wv, vp, M, CKV_, C_);

    // RoPE on q and k
    int tq = B_ * T_ * H_ * 64;
    rope_kernel<<<(tq + 255) / 256, 256>>>(qp, sp, cp, H_, C_, tq);
    int tk = B_ * T_ * HKV_ * 64;
    rope_kernel<<<(tk + 255) / 256, 256>>>(kp, sp, cp, HKV_, CKV_, tk);

    // Causal flash attention
    attn_kernel<<<dim3(T_ / 64, H_, B_), 256, ATTN_SMEM_BYTES>>>();

    // Output projection
    hgemm<<<dim3(C_ / BN, M / BM), 256>>>(yp, wo, out, M, C_, C_);
}

// round 7
// speedup vs baseline: 1.5443x; 1.2979x over previous
#include <cuda_runtime.h>
#include <cuda_bf16.h>
#include <mma.h>
#include <cstdint>
#include <math.h>

using namespace nvcuda;

#define B_   8
#define T_   1024
#define C_   2048
#define H_   16
#define HKV_ 4
#define HD_  128
#define CKV_ 512
#define MTOT (B_ * T_)      // 8192
#define NQKV 3072           // 2048 | 512 | 512

// Scratch (device globals: allocation-free per harness rules)
__device__ float g_q[(size_t)MTOT * C_];
__device__ float g_k[(size_t)MTOT * CKV_];
__device__ float g_v[(size_t)MTOT * CKV_];
__device__ float g_y[(size_t)MTOT * C_];
__device__ __nv_bfloat16 g_xhi[(size_t)MTOT * C_];
__device__ __nv_bfloat16 g_xlo[(size_t)MTOT * C_];
__device__ __nv_bfloat16 g_yhi[(size_t)MTOT * C_];
__device__ __nv_bfloat16 g_ylo[(size_t)MTOT * C_];
__device__ __nv_bfloat16 g_whi[(size_t)C_ * NQKV];
__device__ __nv_bfloat16 g_wlo[(size_t)C_ * NQKV];
__device__ __nv_bfloat16 g_wohi[(size_t)C_ * C_];
__device__ __nv_bfloat16 g_wolo[(size_t)C_ * C_];

__device__ __forceinline__ void cpa16(uint32_t saddr, const void* g) {
    asm volatile("cp.async.cg.shared.global [%0], [%1], 16;\n"
                 :: "r"(saddr), "l"(g));
}

// ---------------------------------------------------------------------------
// fp32 -> bf16 (hi, lo) split, vectorized x4
// ---------------------------------------------------------------------------
union BF4 { __nv_bfloat16 b[4]; uint2 u; };

__device__ __forceinline__ void split4(float4 v, __nv_bfloat16* hi,
                                       __nv_bfloat16* lo, size_t i) {
    float f[4] = {v.x, v.y, v.z, v.w};
    BF4 h, l;
#pragma unroll
    for (int j = 0; j < 4; j++) {
        h.b[j] = __float2bfloat16_rn(f[j]);
        l.b[j] = __float2bfloat16_rn(f[j] - __bfloat162float(h.b[j]));
    }
    *(uint2*)(hi + i) = h.u;
    *(uint2*)(lo + i) = l.u;
}

__global__ void split_kernel(const float* __restrict__ in,
                             __nv_bfloat16* __restrict__ hi,
                             __nv_bfloat16* __restrict__ lo, int n)
{
    size_t i = ((size_t)blockIdx.x * blockDim.x + threadIdx.x) * 4;
    if (i >= (size_t)n) return;
    split4(*(const float4*)(in + i), hi, lo, i);
}

// Pack wq|wk|wv -> [2048, 3072] and split
__global__ void packw_kernel(const float* __restrict__ wq,
                             const float* __restrict__ wk,
                             const float* __restrict__ wv,
                             __nv_bfloat16* __restrict__ hi,
                             __nv_bfloat16* __restrict__ lo)
{
    size_t i = ((size_t)blockIdx.x * blockDim.x + threadIdx.x) * 4;
    if (i >= (size_t)C_ * NQKV) return;
    int r = (int)(i / NQKV), j = (int)(i % NQKV);
    const float* src;
    if (j < 2048)      src = wq + (size_t)r * 2048 + j;
    else if (j < 2560) src = wk + (size_t)r * 512 + (j - 2048);
    else               src = wv + (size_t)r * 512 + (j - 2560);
    split4(*(const float4*)src, hi, lo, i);
}

// ---------------------------------------------------------------------------
// Pure-bf16 tensor-core GEMM (pre-split inputs, cp.async double-buffered).
// C = A @ B, A [M,K] row-major bf16 (hi/lo), B [K,N] row-major bf16 (hi/lo).
// acc = AhiBhi + AhiBlo + AloBhi (fp32). Epilogue routes N-segments.
// Tiles: 128x128x32, 256 threads = 8 warps (4 M x 2 N), warp = 32x64.
// ---------------------------------------------------------------------------
#define BM 128
#define BN 128
#define BK 32
#define PA 48     // A tile row stride (bf16), 96B (16B multiple)
#define PB 136    // B tile row stride, 272B
#define ASZ (BM * PA)   // 6144 elems
#define BSZ (BK * PB)   // 4352 elems
#define G2_SMEM ((4 * ASZ + 4 * BSZ) * 2)   // 83968 bytes

__global__ __launch_bounds__(256) void hgemm2(
    const __nv_bfloat16* __restrict__ Ahi, const __nv_bfloat16* __restrict__ Alo,
    const __nv_bfloat16* __restrict__ Bhi, const __nv_bfloat16* __restrict__ Blo,
    int N, int K,
    float* d0, int w0, int b1, float* d1, int w1, int b2, float* d2, int w2)
{
    extern __shared__ __nv_bfloat16 smem[];
    __nv_bfloat16* sA = smem;             // [part*2+stage][ASZ]
    __nv_bfloat16* sB = smem + 4 * ASZ;   // [part*2+stage][BSZ]
    const uint32_t sAb = (uint32_t)__cvta_generic_to_shared(sA);
    const uint32_t sBb = (uint32_t)__cvta_generic_to_shared(sB);

    const int tid = threadIdx.x;
    const int w   = tid >> 5;
    const int warpM = w & 3;
    const int warpN = w >> 2;
    const int m0 = blockIdx.y * BM;
    const int n0 = blockIdx.x * BN;
    const int NCH = K / BK;

    wmma::fragment<wmma::accumulator, 16, 16, 16, float> acc[2][4];
#pragma unroll
    for (int mt = 0; mt < 2; mt++)
#pragma unroll
        for (int nt = 0; nt < 4; nt++)
            wmma::fill_fragment(acc[mt][nt], 0.0f);

#define LOADC(CH, STG) do {                                                   \
        const int k0_ = (CH) * BK;                                            \
        _Pragma("unroll")                                                     \
        for (int it = 0; it < 2; it++) {                                      \
            int v = it * 256 + tid;                                           \
            int ar = v >> 2, ac = (v & 3) * 8;                                \
            size_t ag = (size_t)(m0 + ar) * K + k0_ + ac;                     \
            uint32_t as = (uint32_t)(ar * PA + ac) * 2;                       \
            cpa16(sAb + ((STG) * ASZ) * 2 + as, Ahi + ag);                    \
            cpa16(sAb + ((2 + (STG)) * ASZ) * 2 + as, Alo + ag);              \
            int br = v >> 4, bc = (v & 15) * 8;                               \
            size_t bg = (size_t)(k0_ + br) * N + n0 + bc;                     \
            uint32_t bs = (uint32_t)(br * PB + bc) * 2;                       \
            cpa16(sBb + ((STG) * BSZ) * 2 + bs, Bhi + bg);                    \
            cpa16(sBb + ((2 + (STG)) * BSZ) * 2 + bs, Blo + bg);              \
        }                                                                     \
        asm volatile("cp.async.commit_group;" ::: "memory");                  \
    } while (0)

    LOADC(0, 0);
    LOADC(1, 1);

    for (int c = 0; c < NCH; c++) {
        const int st = c & 1;
        if (c + 1 < NCH) asm volatile("cp.async.wait_group 1;" ::: "memory");
        else             asm volatile("cp.async.wait_group 0;" ::: "memory");
        __syncthreads();

        const __nv_bfloat16* aH = sA + st * ASZ;
        const __nv_bfloat16* aL = sA + (2 + st) * ASZ;
        const __nv_bfloat16* bH = sB + st * BSZ;
        const __nv_bfloat16* bL = sB + (2 + st) * BSZ;

#pragma unroll
        for (int ks = 0; ks < 2; ks++) {
            wmma::fragment<wmma::matrix_a, 16, 16, 16, __nv_bfloat16, wmma::row_major> ahi[2], alo[2];
            wmma::fragment<wmma::matrix_b, 16, 16, 16, __nv_bfloat16, wmma::row_major> bhi[4], blo[4];
#pragma unroll
            for (int mt = 0; mt < 2; mt++) {
                int off = (warpM * 32 + mt * 16) * PA + ks * 16;
                wmma::load_matrix_sync(ahi[mt], aH + off, PA);
                wmma::load_matrix_sync(alo[mt], aL + off, PA);
            }
#pragma unroll
            for (int nt = 0; nt < 4; nt++) {
                int off = (ks * 16) * PB + warpN * 64 + nt * 16;
                wmma::load_matrix_sync(bhi[nt], bH + off, PB);
                wmma::load_matrix_sync(blo[nt], bL + off, PB);
            }
#pragma unroll
            for (int mt = 0; mt < 2; mt++)
#pragma unroll
                for (int nt = 0; nt < 4; nt++) {
                    wmma::mma_sync(acc[mt][nt], ahi[mt], bhi[nt], acc[mt][nt]);
                    wmma::mma_sync(acc[mt][nt], ahi[mt], blo[nt], acc[mt][nt]);
                    wmma::mma_sync(acc[mt][nt], alo[mt], bhi[nt], acc[mt][nt]);
                }
        }
        __syncthreads();
        if (c + 2 < NCH) LOADC(c + 2, st);
    }

    // Route to destination segment (segment boundaries are BN-aligned)
    float* dst; int wd, nc;
    if (n0 < b1)      { dst = d0; wd = w0; nc = n0; }
    else if (n0 < b2) { dst = d1; wd = w1; nc = n0 - b1; }
    else              { dst = d2; wd = w2; nc = n0 - b2; }

#pragma unroll
    for (int mt = 0; mt < 2; mt++)
#pragma unroll
        for (int nt = 0; nt < 4; nt++) {
            float* cp = dst + (size_t)(m0 + warpM * 32 + mt * 16) * wd
                            + nc + warpN * 64 + nt * 16;
            wmma::store_matrix_sync(cp, acc[mt][nt], wd, wmma::mem_row_major);
        }
#undef LOADC
}

// ---------------------------------------------------------------------------
// RoPE: rotates pairs (d, d+64) of each 128-wide head, in place.
// ---------------------------------------------------------------------------
__global__ void rope_kernel(float* __restrict__ p, const float* __restrict__ sp,
                            const float* __restrict__ cp, int nheads, int width,
                            int total)
{
    int idx = blockIdx.x * blockDim.x + threadIdx.x;
    if (idx >= total) return;
    int i = idx & 63;
    int h = (idx >> 6) % nheads;
    int t = (idx / (64 * nheads)) % T_;
    int b = idx / (64 * nheads * T_);
    size_t base = ((size_t)(b * T_ + t)) * width + h * HD_ + i;
    float a = p[base];
    float c = p[base + 64];
    float s0 = sp[t * HD_ + i],      c0 = cp[t * HD_ + i];
    float s1 = sp[t * HD_ + 64 + i], c1 = cp[t * HD_ + 64 + i];
    p[base]      = a * c0 - c * s0;
    p[base + 64] = c * c1 + a * s1;
}

// ---------------------------------------------------------------------------
// Flash attention (causal, online softmax). One CTA = 64 q rows of one (b,h).
// ---------------------------------------------------------------------------
#define QS_  68
#define PS_  65
#define ATTN_SMEM_BYTES ((128 * QS_ * 2 + 64 * 128 + 64 * PS_) * 4)

__global__ __launch_bounds__(256) void attn_kernel()
{
    extern __shared__ float sm[];
    float* Qs = sm;
    float* Ks = Qs + 128 * QS_;
    float* Vs = Ks + 128 * QS_;
    float* Ps = Vs + 64 * 128;

    const int qt  = blockIdx.x;
    const int h   = blockIdx.y;
    const int b   = blockIdx.z;
    const int q0  = qt * 64;
    const int kvh = h & 3;
    const int tid = threadIdx.x;
    const int tRow = tid >> 4;
    const int tCol = tid & 15;

    const float scale = 0.08838834764831845f;

    const float* qg = g_q + ((size_t)(b * T_ + q0)) * C_ + h * HD_;
    for (int v = tid; v < 64 * 32; v += 256) {
        int r  = v >> 5;
        int d4 = (v & 31) << 2;
        float4 a = *(const float4*)(qg + (size_t)r * C_ + d4);
        Qs[(d4 + 0) * QS_ + r] = a.x * scale;
        Qs[(d4 + 1) * QS_ + r] = a.y * scale;
        Qs[(d4 + 2) * QS_ + r] = a.z * scale;
        Qs[(d4 + 3) * QS_ + r] = a.w * scale;
    }

    float o[4][8];
    float mrow[4], lrow[4];
#pragma unroll
    for (int i = 0; i < 4; i++) {
        mrow[i] = -1e30f;
        lrow[i] = 0.f;
#pragma unroll
        for (int c = 0; c < 8; c++) o[i][c] = 0.f;
    }

    const float* kg = g_k + (size_t)b * T_ * CKV_ + kvh * HD_;
    const float* vg = g_v + (size_t)b * T_ * CKV_ + kvh * HD_;

    for (int kt = 0; kt <= qt; kt++) {
        const int k0 = kt * 64;
        __syncthreads();
        for (int v = tid; v < 64 * 32; v += 256) {
            int r  = v >> 5;
            int d4 = (v & 31) << 2;
            float4 a = *(const float4*)(kg + (size_t)(k0 + r) * CKV_ + d4);
            Ks[(d4 + 0) * QS_ + r] = a.x;
            Ks[(d4 + 1) * QS_ + r] = a.y;
            Ks[(d4 + 2) * QS_ + r] = a.z;
            Ks[(d4 + 3) * QS_ + r] = a.w;
            *(float4*)(Vs + r * 128 + d4) =
                *(const float4*)(vg + (size_t)(k0 + r) * CKV_ + d4);
        }
        __syncthreads();

        float s[4][4];
#pragma unroll
        for (int i = 0; i < 4; i++)
#pragma unroll
            for (int j = 0; j < 4; j++) s[i][j] = 0.f;

        for (int d = 0; d < 128; d++) {
            float qa[4], kb[4];
            *(float4*)qa = *(const float4*)(Qs + d * QS_ + tRow * 4);
            *(float4*)kb = *(const float4*)(Ks + d * QS_ + tCol * 4);
#pragma unroll
            for (int i = 0; i < 4; i++)
#pragma unroll
                for (int j = 0; j < 4; j++)
                    s[i][j] = fmaf(qa[i], kb[j], s[i][j]);
        }

        if (kt == qt) {
#pragma unroll
            for (int i = 0; i < 4; i++)
#pragma unroll
                for (int j = 0; j < 4; j++)
                    if (k0 + tCol * 4 + j > q0 + tRow * 4 + i) s[i][j] = -1e30f;
        }

#pragma unroll
        for (int i = 0; i < 4; i++) {
            float rm = fmaxf(fmaxf(s[i][0], s[i][1]), fmaxf(s[i][2], s[i][3]));
#pragma unroll
            for (int off = 8; off; off >>= 1)
                rm = fmaxf(rm, __shfl_xor_sync(0xffffffffu, rm, off, 16));
            float mn = fmaxf(mrow[i], rm);
            float al = __expf(mrow[i] - mn);
            mrow[i] = mn;
            float rs = 0.f;
#pragma unroll
            for (int j = 0; j < 4; j++) {
                float pv = __expf(s[i][j] - mn);
                rs += pv;
                Ps[(tRow * 4 + i) * PS_ + tCol * 4 + j] = pv;
            }
#pragma unroll
            for (int off = 8; off; off >>= 1)
                rs += __shfl_xor_sync(0xffffffffu, rs, off, 16);
            lrow[i] = lrow[i] * al + rs;
#pragma unroll
            for (int c = 0; c < 8; c++) o[i][c] *= al;
        }
        __syncthreads();

#pragma unroll 2
        for (int kk = 0; kk < 64; kk++) {
            float vv[8];
            *(float4*)vv       = *(const float4*)(Vs + kk * 128 + tCol * 8);
            *(float4*)(vv + 4) = *(const float4*)(Vs + kk * 128 + tCol * 8 + 4);
#pragma unroll
            for (int i = 0; i < 4; i++) {
                float pp = Ps[(tRow * 4 + i) * PS_ + kk];
#pragma unroll
                for (int c = 0; c < 8; c++)
                    o[i][c] = fmaf(pp, vv[c], o[i][c]);
            }
        }
    }

    float* yg = g_y + ((size_t)(b * T_ + q0)) * C_ + h * HD_;
#pragma unroll
    for (int i = 0; i < 4; i++) {
        float inv = 1.f / lrow[i];
        float* dst = yg + (size_t)(tRow * 4 + i) * C_ + tCol * 8;
        *(float4*)dst       = make_float4(o[i][0] * inv, o[i][1] * inv,
                                          o[i][2] * inv, o[i][3] * inv);
        *(float4*)(dst + 4) = make_float4(o[i][4] * inv, o[i][5] * inv,
                                          o[i][6] * inv, o[i][7] * inv);
    }
}

// ---------------------------------------------------------------------------
extern "C" void kernel_launch(void* const* d_in, const int* in_sizes, int n_in,
                              void* d_out, int out_size)
{
    const float* x  = (const float*)d_in[0];
    const float* wq = (const float*)d_in[1];
    const float* wk = (const float*)d_in[2];
    const float* wv = (const float*)d_in[3];
    const float* wo = (const float*)d_in[4];
    const float* sp = (const float*)d_in[5];
    const float* cp = (const float*)d_in[6];
    float* out = (float*)d_out;

    float *qp, *kp, *vp, *yp;
    __nv_bfloat16 *xhi, *xlo, *yhi, *ylo, *whi, *wlo, *wohi, *wolo;
    cudaGetSymbolAddress((void**)&qp, g_q);
    cudaGetSymbolAddress((void**)&kp, g_k);
    cudaGetSymbolAddress((void**)&vp, g_v);
    cudaGetSymbolAddress((void**)&yp, g_y);
    cudaGetSymbolAddress((void**)&xhi, g_xhi);
    cudaGetSymbolAddress((void**)&xlo, g_xlo);
    cudaGetSymbolAddress((void**)&yhi, g_yhi);
    cudaGetSymbolAddress((void**)&ylo, g_ylo);
    cudaGetSymbolAddress((void**)&whi, g_whi);
    cudaGetSymbolAddress((void**)&wlo, g_wlo);
    cudaGetSymbolAddress((void**)&wohi, g_wohi);
    cudaGetSymbolAddress((void**)&wolo, g_wolo);

    cudaFuncSetAttribute(attn_kernel, cudaFuncAttributeMaxDynamicSharedMemorySize,
                         ATTN_SMEM_BYTES);
    cudaFuncSetAttribute(hgemm2, cudaFuncAttributeMaxDynamicSharedMemorySize,
                         G2_SMEM);

    // Pre-split inputs/weights to bf16 hi/lo
    int nx = MTOT * C_;
    split_kernel<<<nx / 4 / 256, 256>>>(x, xhi, xlo, nx);
    packw_kernel<<<(C_ * NQKV / 4) / 256, 256>>>(wq, wk, wv, whi, wlo);
    split_kernel<<<(C_ * C_ / 4) / 256, 256>>>(wo, wohi, wolo, C_ * C_);

    // Fused QKV projection: N = 2048 | 512 | 512
    hgemm2<<<dim3(NQKV / BN, MTOT / BM), 256, G2_SMEM>>>(
        xhi, xlo, whi, wlo, NQKV, C_,
        qp, C_, 2048, kp, CKV_, 2560, vp, CKV_);

    // RoPE on q and k
    int tq = MTOT * H_ * 64;
    rope_kernel<<<(tq + 255) / 256, 256>>>(qp, sp, cp, H_, C_, tq);
    int tk = MTOT * HKV_ * 64;
    rope_kernel<<<(tk + 255) / 256, 256>>>(kp, sp, cp, HKV_, CKV_, tk);

    // Causal flash attention
    attn_kernel<<<dim3(T_ / 64, H_, B_), 256, ATTN_SMEM_BYTES>>>();

    // Output projection
    split_kernel<<<nx / 4 / 256, 256>>>(yp, yhi, ylo, nx);
    hgemm2<<<dim3(C_ / BN, MTOT / BM), 256, G2_SMEM>>>(
        yhi, ylo, wohi, wolo, C_, C_,
        out, C_, 1 << 30, out, C_, 1 << 30, out, C_);
}